// round 8
// baseline (speedup 1.0000x reference)
#include <cuda_runtime.h>
#include <cuda_bf16.h>
#include <math.h>
#include <stdint.h>

// Problem constants
#define BATCH 2
#define SEQ   2048
#define DIM   1024
#define HEADS 16
#define HDIM  64
#define MROWS (BATCH * SEQ)   // 4096

typedef __nv_bfloat16 bf16;

// Pre-split scratch (device globals: allocation-free)
__device__ bf16 g_xh[MROWS * DIM], g_xl[MROWS * DIM];      // activation input
__device__ bf16 g_wh[DIM * DIM],   g_wl[DIM * DIM];        // current weight
__device__ bf16 g_qh[MROWS * DIM], g_ql[MROWS * DIM];      // projected Q (x8)
__device__ bf16 g_kh[MROWS * DIM], g_kl[MROWS * DIM];      // projected K
__device__ bf16 g_vth[BATCH * HEADS * HDIM * SEQ];         // projected V^T
__device__ bf16 g_vtl[BATCH * HEADS * HDIM * SEQ];
__device__ bf16 g_ah[MROWS * DIM], g_al[MROWS * DIM];      // attention out

// ===========================================================================
// Helpers
// ===========================================================================
__device__ __forceinline__ uint32_t smem_u32(const void* p) {
    uint32_t a;
    asm("{ .reg .u64 t; cvta.to.shared.u64 t, %1; cvt.u32.u64 %0, t; }"
        : "=r"(a) : "l"(p));
    return a;
}
__device__ __forceinline__ void cp16(uint32_t dst, const void* src) {
    asm volatile("cp.async.cg.shared.global [%0], [%1], 16;"
                 :: "r"(dst), "l"(src));
}
#define CP_COMMIT() asm volatile("cp.async.commit_group;" ::: "memory")
#define CP_WAIT1()  asm volatile("cp.async.wait_group 1;" ::: "memory")

__device__ __forceinline__ void split2(float x0, float x1,
                                       uint32_t& hi, uint32_t& lo) {
    bf16 h0 = __float2bfloat16_rn(x0);
    bf16 h1 = __float2bfloat16_rn(x1);
    float r0 = x0 - __bfloat162float(h0);
    float r1 = x1 - __bfloat162float(h1);
    __nv_bfloat162 hh = __halves2bfloat162(h0, h1);
    __nv_bfloat162 ll = __halves2bfloat162(__float2bfloat16_rn(r0),
                                           __float2bfloat16_rn(r1));
    hi = *reinterpret_cast<uint32_t*>(&hh);
    lo = *reinterpret_cast<uint32_t*>(&ll);
}

__device__ __forceinline__ void mma_bf16(float* c, uint32_t a0, uint32_t a1,
                                         uint32_t a2, uint32_t a3,
                                         uint32_t b0, uint32_t b1) {
    asm volatile(
        "mma.sync.aligned.m16n8k16.row.col.f32.bf16.bf16.f32 "
        "{%0,%1,%2,%3}, {%4,%5,%6,%7}, {%8,%9}, {%0,%1,%2,%3};"
        : "+f"(c[0]), "+f"(c[1]), "+f"(c[2]), "+f"(c[3])
        : "r"(a0), "r"(a1), "r"(a2), "r"(a3), "r"(b0), "r"(b1));
}

// ===========================================================================
// Convert: fp32 -> bf16 hi/lo (one pass, coalesced)
// ===========================================================================
__global__ __launch_bounds__(256) void convert_split(
    const float* __restrict__ src, bf16* __restrict__ dh,
    bf16* __restrict__ dl, int n)
{
    int base = (blockIdx.x * 256 + threadIdx.x) * 4;
    if (base >= n) return;
    float4 v = *(const float4*)(src + base);
    uint32_t h0, l0, h1, l1;
    split2(v.x, v.y, h0, l0);
    split2(v.z, v.w, h1, l1);
    *(uint32_t*)(dh + base) = h0; *(uint32_t*)(dh + base + 2) = h1;
    *(uint32_t*)(dl + base) = l0; *(uint32_t*)(dl + base + 2) = l1;
}

// ===========================================================================
// GEMM: C[M,N] = A[M,K]*B[N,K]^T + bias.  Pre-split bf16 inputs, 3-stage
// cp.async pipeline, 1 sync/iter. M=4096,N=1024,K=1024. BK=16.
// mode 0: fp32 out. mode 1: split bf16 out (scaled). mode 2: split V^T out.
// ===========================================================================
#define GSTAGE 16384     // bytes per stage: AH|AL|BH|BL, each 128x16 halfs

__global__ __launch_bounds__(256, 1) void gemm_pre(
    const bf16* __restrict__ AH, const bf16* __restrict__ AL,
    const bf16* __restrict__ BH, const bf16* __restrict__ BL,
    const float* __restrict__ bias, int mode, float scale,
    float* __restrict__ Cf, bf16* __restrict__ CH, bf16* __restrict__ CL,
    bf16* __restrict__ VTH, bf16* __restrict__ VTL)
{
    extern __shared__ __align__(16) char gsm[];
    const uint32_t sb = smem_u32(gsm);

    const int tid = threadIdx.x;
    const int lane = tid & 31;
    const int wid = tid >> 5;
    const int wm = wid >> 2, wn = wid & 3;
    const int g = lane >> 2, t = lane & 3;
    const int bx = blockIdx.x, by = blockIdx.y;

    // cp.async chunk plan: 4 chunks/thread/stage
    const bf16* src[4];
    uint32_t dstoff[4];
#pragma unroll
    for (int p = 0; p < 4; p++) {
        int idx = tid + p * 256;
        int sub = idx >> 8, r = (idx >> 1) & 127, c = idx & 1;
        const bf16* s;
        if (sub == 0)      s = AH + (size_t)(by * 128 + r) * DIM + c * 8;
        else if (sub == 1) s = AL + (size_t)(by * 128 + r) * DIM + c * 8;
        else if (sub == 2) s = BH + (size_t)(bx * 128 + r) * DIM + c * 8;
        else               s = BL + (size_t)(bx * 128 + r) * DIM + c * 8;
        src[p] = s;
        dstoff[p] = (uint32_t)(sub * 4096 + r * 32 + c * 16);
    }
    auto loadG = [&](int it, int st) {
#pragma unroll
        for (int p = 0; p < 4; p++)
            cp16(sb + st * GSTAGE + dstoff[p], src[p] + it * 16);
    };

    float acc[4][4][4];
#pragma unroll
    for (int i = 0; i < 4; i++)
#pragma unroll
        for (int j = 0; j < 4; j++)
#pragma unroll
            for (int e = 0; e < 4; e++) acc[i][j][e] = 0.0f;

    loadG(0, 0); CP_COMMIT();
    loadG(1, 1); CP_COMMIT();

    const int KITERS = DIM / 16;   // 64
    for (int it = 0; it < KITERS; it++) {
        CP_WAIT1();
        __syncthreads();
        const char* S = gsm + (it % 3) * GSTAGE;

        uint32_t Ahi[4][4], Alo[4][4], Bhi[4][2], Blo[4][2];
#pragma unroll
        for (int mf = 0; mf < 4; mf++) {
            int r0 = wm * 64 + mf * 16 + g;
            Ahi[mf][0] = *(uint32_t*)(S + r0 * 32 + 4 * t);
            Ahi[mf][1] = *(uint32_t*)(S + (r0 + 8) * 32 + 4 * t);
            Ahi[mf][2] = *(uint32_t*)(S + r0 * 32 + 4 * t + 16);
            Ahi[mf][3] = *(uint32_t*)(S + (r0 + 8) * 32 + 4 * t + 16);
            Alo[mf][0] = *(uint32_t*)(S + 4096 + r0 * 32 + 4 * t);
            Alo[mf][1] = *(uint32_t*)(S + 4096 + (r0 + 8) * 32 + 4 * t);
            Alo[mf][2] = *(uint32_t*)(S + 4096 + r0 * 32 + 4 * t + 16);
            Alo[mf][3] = *(uint32_t*)(S + 4096 + (r0 + 8) * 32 + 4 * t + 16);
        }
#pragma unroll
        for (int nf = 0; nf < 4; nf++) {
            int n = wn * 32 + nf * 8 + g;
            Bhi[nf][0] = *(uint32_t*)(S + 8192 + n * 32 + 4 * t);
            Bhi[nf][1] = *(uint32_t*)(S + 8192 + n * 32 + 4 * t + 16);
            Blo[nf][0] = *(uint32_t*)(S + 12288 + n * 32 + 4 * t);
            Blo[nf][1] = *(uint32_t*)(S + 12288 + n * 32 + 4 * t + 16);
        }

#pragma unroll
        for (int mf = 0; mf < 4; mf++)
#pragma unroll
            for (int nf = 0; nf < 4; nf++) {
                float* c = acc[mf][nf];
                mma_bf16(c, Ahi[mf][0], Ahi[mf][1], Ahi[mf][2], Ahi[mf][3],
                         Bhi[nf][0], Bhi[nf][1]);
                mma_bf16(c, Ahi[mf][0], Ahi[mf][1], Ahi[mf][2], Ahi[mf][3],
                         Blo[nf][0], Blo[nf][1]);
                mma_bf16(c, Alo[mf][0], Alo[mf][1], Alo[mf][2], Alo[mf][3],
                         Bhi[nf][0], Bhi[nf][1]);
            }

        if (it + 2 < KITERS) loadG(it + 2, (it + 2) % 3);
        CP_COMMIT();
    }

    // ---- epilogue ----
#pragma unroll
    for (int mf = 0; mf < 4; mf++) {
#pragma unroll
        for (int nf = 0; nf < 4; nf++) {
            int row0 = by * 128 + wm * 64 + mf * 16 + g;
            int col = bx * 128 + wn * 32 + nf * 8 + 2 * t;
            float b0 = bias[col], b1 = bias[col + 1];
            float v0 = (acc[mf][nf][0] + b0) * scale;
            float v1 = (acc[mf][nf][1] + b1) * scale;
            float v2 = (acc[mf][nf][2] + b0) * scale;
            float v3 = (acc[mf][nf][3] + b1) * scale;
            if (mode == 0) {
                float2 o0 = {v0, v1}, o1 = {v2, v3};
                *(float2*)(Cf + (size_t)row0 * DIM + col) = o0;
                *(float2*)(Cf + (size_t)(row0 + 8) * DIM + col) = o1;
            } else if (mode == 1) {
                uint32_t h01, l01, h23, l23;
                split2(v0, v1, h01, l01);
                split2(v2, v3, h23, l23);
                *(uint32_t*)(CH + (size_t)row0 * DIM + col) = h01;
                *(uint32_t*)(CL + (size_t)row0 * DIM + col) = l01;
                *(uint32_t*)(CH + (size_t)(row0 + 8) * DIM + col) = h23;
                *(uint32_t*)(CL + (size_t)(row0 + 8) * DIM + col) = l23;
            } else {
                // V^T scatter: vt[(b*16+h)*64+d][token]
                int bb = row0 >> 11;
                int s0 = row0 & 2047, s1 = (row0 + 8) & 2047;
                int hh = col >> 6, d = col & 63;
                size_t vr = ((size_t)(bb * 16 + hh) * 64 + d) * SEQ;
                bf16 h; float v;
                v = v0; h = __float2bfloat16_rn(v);
                VTH[vr + s0] = h;
                VTL[vr + s0] = __float2bfloat16_rn(v - __bfloat162float(h));
                v = v1; h = __float2bfloat16_rn(v);
                VTH[vr + SEQ + s0] = h;
                VTL[vr + SEQ + s0] = __float2bfloat16_rn(v - __bfloat162float(h));
                v = v2; h = __float2bfloat16_rn(v);
                VTH[vr + s1] = h;
                VTL[vr + s1] = __float2bfloat16_rn(v - __bfloat162float(h));
                v = v3; h = __float2bfloat16_rn(v);
                VTH[vr + SEQ + s1] = h;
                VTL[vr + SEQ + s1] = __float2bfloat16_rn(v - __bfloat162float(h));
            }
        }
    }
}

// ===========================================================================
// Tensor-core flash attention: pre-split bf16 inputs, 3-stage cp.async K/V
// pipeline (1 sync/iter), round-6 MMA ordering. Writes split bf16 output.
// Block: 128 q rows x one (b,h), 256 threads, K-tile = 64 tokens.
// ===========================================================================
#define AROW 144                         // bytes per smem row (128 data + 16)
#define ASUB (64 * AROW)                 // 9216 bytes per sub-tile
#define ASTAGE (4 * ASUB)                // KH|KL|VTH|VTL = 36864 bytes
#define ATT_SMEM (3 * ASTAGE)            // 110592 bytes

__global__ __launch_bounds__(256, 1) void flash_attn_pre(
    const bf16* __restrict__ QH, const bf16* __restrict__ QL,
    const bf16* __restrict__ KH_g, const bf16* __restrict__ KL_g,
    const bf16* __restrict__ VTH_g, const bf16* __restrict__ VTL_g,
    bf16* __restrict__ OH, bf16* __restrict__ OL)
{
    extern __shared__ __align__(16) char smem[];
    const uint32_t sb = smem_u32(smem);

    const int tid = threadIdx.x;
    const int lane = tid & 31;
    const int w = tid >> 5;
    const int g = lane >> 2, t = lane & 3;

    const int bh = blockIdx.y;
    const int b = bh >> 4, h = bh & 15;
    const int q0 = blockIdx.x * 128;

    // cp.async chunk plan: 8 chunks/thread/stage
    const bf16* src[8];
    uint32_t dstoff[8];
    int step[8];
#pragma unroll
    for (int p = 0; p < 8; p++) {
        int idx = tid + p * 256;
        int sub = idx >> 9, r = (idx >> 3) & 63, c = idx & 7;
        const bf16* s;
        int st;
        if (sub == 0) {
            s = KH_g + ((size_t)b * SEQ + r) * DIM + h * HDIM + c * 8;
            st = 64 * DIM;
        } else if (sub == 1) {
            s = KL_g + ((size_t)b * SEQ + r) * DIM + h * HDIM + c * 8;
            st = 64 * DIM;
        } else if (sub == 2) {
            s = VTH_g + ((size_t)bh * HDIM + r) * SEQ + c * 8;
            st = 64;
        } else {
            s = VTL_g + ((size_t)bh * HDIM + r) * SEQ + c * 8;
            st = 64;
        }
        src[p] = s;
        step[p] = st;
        dstoff[p] = (uint32_t)(sub * ASUB + r * AROW + c * 16);
    }
    auto loadKV = [&](int it, int st) {
#pragma unroll
        for (int p = 0; p < 8; p++)
            cp16(sb + st * ASTAGE + dstoff[p], src[p] + (size_t)it * step[p]);
    };

    loadKV(0, 0); CP_COMMIT();
    loadKV(1, 1); CP_COMMIT();

    // ---- Q fragments direct from global (once) ----
    uint32_t qh[4][4], ql[4][4];
    {
        const bf16* qbh0 = QH + ((size_t)b * SEQ + q0 + w * 16 + g) * DIM + h * HDIM;
        const bf16* qbh8 = qbh0 + 8 * DIM;
        const bf16* qbl0 = QL + ((size_t)b * SEQ + q0 + w * 16 + g) * DIM + h * HDIM;
        const bf16* qbl8 = qbl0 + 8 * DIM;
#pragma unroll
        for (int kf = 0; kf < 4; kf++) {
            qh[kf][0] = *(const uint32_t*)(qbh0 + kf * 16 + 2 * t);
            qh[kf][1] = *(const uint32_t*)(qbh8 + kf * 16 + 2 * t);
            qh[kf][2] = *(const uint32_t*)(qbh0 + kf * 16 + 8 + 2 * t);
            qh[kf][3] = *(const uint32_t*)(qbh8 + kf * 16 + 8 + 2 * t);
            ql[kf][0] = *(const uint32_t*)(qbl0 + kf * 16 + 2 * t);
            ql[kf][1] = *(const uint32_t*)(qbl8 + kf * 16 + 2 * t);
            ql[kf][2] = *(const uint32_t*)(qbl0 + kf * 16 + 8 + 2 * t);
            ql[kf][3] = *(const uint32_t*)(qbl8 + kf * 16 + 8 + 2 * t);
        }
    }

    float m0 = -INFINITY, m1 = -INFINITY, l0 = 0.0f, l1 = 0.0f;
    float acc[8][4];
#pragma unroll
    for (int nf = 0; nf < 8; nf++)
#pragma unroll
        for (int e = 0; e < 4; e++) acc[nf][e] = 0.0f;

    const int NTILES = SEQ / 64;   // 32
    for (int it = 0; it < NTILES; it++) {
        CP_WAIT1();
        __syncthreads();
        const char* S = smem + (it % 3) * ASTAGE;
        const char* SKH = S;
        const char* SKL = S + ASUB;
        const char* SVH = S + 2 * ASUB;
        const char* SVL = S + 3 * ASUB;

        // ---- scores (round-6 ordering: nf outer, 3 terms per kf) ----
        float s[8][4];
#pragma unroll
        for (int nf = 0; nf < 8; nf++)
#pragma unroll
            for (int e = 0; e < 4; e++) s[nf][e] = 0.0f;

#pragma unroll
        for (int nf = 0; nf < 8; nf++) {
            const int rowoff = (nf * 8 + g) * AROW;
#pragma unroll
            for (int kf = 0; kf < 4; kf++) {
                uint32_t bh0 = *(uint32_t*)(SKH + rowoff + kf * 32 + 4 * t);
                uint32_t bh1 = *(uint32_t*)(SKH + rowoff + kf * 32 + 4 * t + 16);
                uint32_t bl0 = *(uint32_t*)(SKL + rowoff + kf * 32 + 4 * t);
                uint32_t bl1 = *(uint32_t*)(SKL + rowoff + kf * 32 + 4 * t + 16);
                mma_bf16(s[nf], qh[kf][0], qh[kf][1], qh[kf][2], qh[kf][3], bh0, bh1);
                mma_bf16(s[nf], ql[kf][0], ql[kf][1], ql[kf][2], ql[kf][3], bh0, bh1);
                mma_bf16(s[nf], qh[kf][0], qh[kf][1], qh[kf][2], qh[kf][3], bl0, bl1);
            }
        }

        // ---- online softmax ----
        float tm0 = -INFINITY, tm1 = -INFINITY;
#pragma unroll
        for (int nf = 0; nf < 8; nf++) {
            tm0 = fmaxf(tm0, fmaxf(s[nf][0], s[nf][1]));
            tm1 = fmaxf(tm1, fmaxf(s[nf][2], s[nf][3]));
        }
        tm0 = fmaxf(tm0, __shfl_xor_sync(0xffffffffu, tm0, 1));
        tm0 = fmaxf(tm0, __shfl_xor_sync(0xffffffffu, tm0, 2));
        tm1 = fmaxf(tm1, __shfl_xor_sync(0xffffffffu, tm1, 1));
        tm1 = fmaxf(tm1, __shfl_xor_sync(0xffffffffu, tm1, 2));

        float mn0 = fmaxf(m0, tm0), mn1 = fmaxf(m1, tm1);
        float c0 = __expf(m0 - mn0), c1 = __expf(m1 - mn1);
        m0 = mn0; m1 = mn1;

        float ls0 = 0.0f, ls1 = 0.0f;
#pragma unroll
        for (int nf = 0; nf < 8; nf++) {
            s[nf][0] = __expf(s[nf][0] - mn0);
            s[nf][1] = __expf(s[nf][1] - mn0);
            s[nf][2] = __expf(s[nf][2] - mn1);
            s[nf][3] = __expf(s[nf][3] - mn1);
            ls0 += s[nf][0] + s[nf][1];
            ls1 += s[nf][2] + s[nf][3];
        }
        ls0 += __shfl_xor_sync(0xffffffffu, ls0, 1);
        ls0 += __shfl_xor_sync(0xffffffffu, ls0, 2);
        ls1 += __shfl_xor_sync(0xffffffffu, ls1, 1);
        ls1 += __shfl_xor_sync(0xffffffffu, ls1, 2);
        l0 = l0 * c0 + ls0;
        l1 = l1 * c1 + ls1;

#pragma unroll
        for (int nf = 0; nf < 8; nf++) {
            acc[nf][0] *= c0; acc[nf][1] *= c0;
            acc[nf][2] *= c1; acc[nf][3] *= c1;
        }

        // ---- pack P (registers only) ----
        uint32_t ph[4][4], pl[4][4];
#pragma unroll
        for (int kf = 0; kf < 4; kf++) {
            const float* p0 = s[2 * kf];
            const float* p1 = s[2 * kf + 1];
            split2(p0[0], p0[1], ph[kf][0], pl[kf][0]);
            split2(p0[2], p0[3], ph[kf][1], pl[kf][1]);
            split2(p1[0], p1[1], ph[kf][2], pl[kf][2]);
            split2(p1[2], p1[3], ph[kf][3], pl[kf][3]);
        }

        // ---- acc += P * V (round-6 ordering) ----
#pragma unroll
        for (int nf = 0; nf < 8; nf++) {
            const int rowoff = (nf * 8 + g) * AROW;
#pragma unroll
            for (int kf = 0; kf < 4; kf++) {
                uint32_t bh0 = *(uint32_t*)(SVH + rowoff + kf * 32 + 4 * t);
                uint32_t bh1 = *(uint32_t*)(SVH + rowoff + kf * 32 + 4 * t + 16);
                uint32_t bl0 = *(uint32_t*)(SVL + rowoff + kf * 32 + 4 * t);
                uint32_t bl1 = *(uint32_t*)(SVL + rowoff + kf * 32 + 4 * t + 16);
                mma_bf16(acc[nf], ph[kf][0], ph[kf][1], ph[kf][2], ph[kf][3], bh0, bh1);
                mma_bf16(acc[nf], pl[kf][0], pl[kf][1], pl[kf][2], pl[kf][3], bh0, bh1);
                mma_bf16(acc[nf], ph[kf][0], ph[kf][1], ph[kf][2], ph[kf][3], bl0, bl1);
            }
        }

        if (it + 2 < NTILES) loadKV(it + 2, (it + 2) % 3);
        CP_COMMIT();
    }

    // ---- epilogue: normalized, split bf16 out ----
    const float inv0 = 1.0f / l0;
    const float inv1 = 1.0f / l1;
    const size_t row0 = (size_t)b * SEQ + q0 + w * 16 + g;
#pragma unroll
    for (int nf = 0; nf < 8; nf++) {
        const int col = h * HDIM + nf * 8 + 2 * t;
        uint32_t h01, l01, h23, l23;
        split2(acc[nf][0] * inv0, acc[nf][1] * inv0, h01, l01);
        split2(acc[nf][2] * inv1, acc[nf][3] * inv1, h23, l23);
        *(uint32_t*)(OH + row0 * DIM + col) = h01;
        *(uint32_t*)(OL + row0 * DIM + col) = l01;
        *(uint32_t*)(OH + (row0 + 8) * DIM + col) = h23;
        *(uint32_t*)(OL + (row0 + 8) * DIM + col) = l23;
    }
}

// ---------------------------------------------------------------------------
extern "C" void kernel_launch(void* const* d_in, const int* in_sizes, int n_in,
                              void* d_out, int out_size)
{
    (void)in_sizes; (void)n_in; (void)out_size;
    const float* query = (const float*)d_in[0];
    const float* key   = (const float*)d_in[1];
    const float* value = (const float*)d_in[2];
    const float* Wq = (const float*)d_in[3];
    const float* bq = (const float*)d_in[4];
    const float* Wk = (const float*)d_in[5];
    const float* bk = (const float*)d_in[6];
    const float* Wv = (const float*)d_in[7];
    const float* bv = (const float*)d_in[8];
    const float* Wo = (const float*)d_in[9];
    const float* bo = (const float*)d_in[10];
    float* out = (float*)d_out;

    bf16 *xh, *xl, *wh, *wl, *qh, *ql, *kh, *kl, *vth, *vtl, *ah, *al;
    cudaGetSymbolAddress((void**)&xh, g_xh);
    cudaGetSymbolAddress((void**)&xl, g_xl);
    cudaGetSymbolAddress((void**)&wh, g_wh);
    cudaGetSymbolAddress((void**)&wl, g_wl);
    cudaGetSymbolAddress((void**)&qh, g_qh);
    cudaGetSymbolAddress((void**)&ql, g_ql);
    cudaGetSymbolAddress((void**)&kh, g_kh);
    cudaGetSymbolAddress((void**)&kl, g_kl);
    cudaGetSymbolAddress((void**)&vth, g_vth);
    cudaGetSymbolAddress((void**)&vtl, g_vtl);
    cudaGetSymbolAddress((void**)&ah, g_ah);
    cudaGetSymbolAddress((void**)&al, g_al);

    static bool attrSet = false;
    if (!attrSet) {
        cudaFuncSetAttribute(gemm_pre,
                             cudaFuncAttributeMaxDynamicSharedMemorySize,
                             3 * GSTAGE);
        cudaFuncSetAttribute(flash_attn_pre,
                             cudaFuncAttributeMaxDynamicSharedMemorySize,
                             ATT_SMEM);
        attrSet = true;
    }

    const int NX = MROWS * DIM;   // 4M
    const int NW = DIM * DIM;     // 1M
    dim3 gemmGrid(DIM / 128, MROWS / 128);   // (8, 32)

    // Q projection (scale 8 folded)
    convert_split<<<NX / 1024, 256>>>(query, xh, xl, NX);
    convert_split<<<NW / 1024, 256>>>(Wq, wh, wl, NW);
    gemm_pre<<<gemmGrid, 256, 3 * GSTAGE>>>(xh, xl, wh, wl, bq, 1, 8.0f,
                                            nullptr, qh, ql, nullptr, nullptr);
    // K projection
    convert_split<<<NX / 1024, 256>>>(key, xh, xl, NX);
    convert_split<<<NW / 1024, 256>>>(Wk, wh, wl, NW);
    gemm_pre<<<gemmGrid, 256, 3 * GSTAGE>>>(xh, xl, wh, wl, bk, 1, 1.0f,
                                            nullptr, kh, kl, nullptr, nullptr);
    // V projection (transposed split output)
    convert_split<<<NX / 1024, 256>>>(value, xh, xl, NX);
    convert_split<<<NW / 1024, 256>>>(Wv, wh, wl, NW);
    gemm_pre<<<gemmGrid, 256, 3 * GSTAGE>>>(xh, xl, wh, wl, bv, 2, 1.0f,
                                            nullptr, nullptr, nullptr, vth, vtl);
    // Attention
    dim3 attnGrid(SEQ / 128, BATCH * HEADS);  // (16, 32)
    flash_attn_pre<<<attnGrid, 256, ATT_SMEM>>>(qh, ql, kh, kl, vth, vtl, ah, al);
    // Output projection
    convert_split<<<NW / 1024, 256>>>(Wo, wh, wl, NW);
    gemm_pre<<<gemmGrid, 256, 3 * GSTAGE>>>(ah, al, wh, wl, bo, 0, 1.0f,
                                            out, nullptr, nullptr, nullptr, nullptr);
}

// round 9
// speedup vs baseline: 1.1288x; 1.1288x over previous
#include <cuda_runtime.h>
#include <cuda_bf16.h>
#include <math.h>
#include <stdint.h>

// Problem constants
#define BATCH 2
#define SEQ   2048
#define DIM   1024
#define HEADS 16
#define HDIM  64
#define MROWS (BATCH * SEQ)   // 4096

// Scratch (device globals: allocation-free)
__device__ float g_Q[MROWS * DIM];
__device__ float g_K[MROWS * DIM];
__device__ float g_V[MROWS * DIM];
__device__ float g_A[MROWS * DIM];

// ===========================================================================
// Helpers
// ===========================================================================
__device__ __forceinline__ uint32_t smem_u32(const void* p) {
    uint32_t a;
    asm("{ .reg .u64 t; cvta.to.shared.u64 t, %1; cvt.u32.u64 %0, t; }"
        : "=r"(a) : "l"(p));
    return a;
}

__device__ __forceinline__ void cp16(uint32_t dst, const void* src) {
    asm volatile("cp.async.cg.shared.global [%0], [%1], 16;"
                 :: "r"(dst), "l"(src));
}
#define CP_COMMIT() asm volatile("cp.async.commit_group;" ::: "memory")
#define CP_WAIT1()  asm volatile("cp.async.wait_group 1;" ::: "memory")

__device__ __forceinline__ void split2(float x0, float x1,
                                       uint32_t& hi, uint32_t& lo) {
    __nv_bfloat16 h0 = __float2bfloat16_rn(x0);
    __nv_bfloat16 h1 = __float2bfloat16_rn(x1);
    float r0 = x0 - __bfloat162float(h0);
    float r1 = x1 - __bfloat162float(h1);
    __nv_bfloat162 hh = __halves2bfloat162(h0, h1);
    __nv_bfloat162 ll = __halves2bfloat162(__float2bfloat16_rn(r0),
                                           __float2bfloat16_rn(r1));
    hi = *reinterpret_cast<uint32_t*>(&hh);
    lo = *reinterpret_cast<uint32_t*>(&ll);
}

__device__ __forceinline__ void mma_bf16(float* c, uint32_t a0, uint32_t a1,
                                         uint32_t a2, uint32_t a3,
                                         uint32_t b0, uint32_t b1) {
    asm volatile(
        "mma.sync.aligned.m16n8k16.row.col.f32.bf16.bf16.f32 "
        "{%0,%1,%2,%3}, {%4,%5,%6,%7}, {%8,%9}, {%0,%1,%2,%3};"
        : "+f"(c[0]), "+f"(c[1]), "+f"(c[2]), "+f"(c[3])
        : "r"(a0), "r"(a1), "r"(a2), "r"(a3), "r"(b0), "r"(b1));
}

__device__ __forceinline__ void ldmx4(uint32_t* r, uint32_t addr) {
    asm volatile(
        "ldmatrix.sync.aligned.m8n8.x4.shared.b16 {%0,%1,%2,%3}, [%4];"
        : "=r"(r[0]), "=r"(r[1]), "=r"(r[2]), "=r"(r[3]) : "r"(addr));
}

// ===========================================================================
// GEMM body: C[M,N] = A[M,K]*B[N,K]^T + bias[N].  M=4096, N=K=1024.
// Round-6 structure verbatim (measured best).
// ===========================================================================
#define BMT 128
#define BNT 128
#define BKT 16
#define SSTR 20

__device__ __forceinline__ void gemm_body(
    const float* __restrict__ A, const float* __restrict__ Bm,
    const float* __restrict__ bias, float* __restrict__ C)
{
    __shared__ float sA[2][BMT * SSTR];
    __shared__ float sB[2][BNT * SSTR];

    const int tid = threadIdx.x;
    const int lane = tid & 31;
    const int wid = tid >> 5;
    const int wm = wid >> 2;
    const int wn = wid & 3;
    const int g = lane >> 2;
    const int t = lane & 3;

    const int bx = blockIdx.x;
    const int by = blockIdx.y;

    const float* Abase = A + (size_t)(by * BMT) * DIM;
    const float* Bbase = Bm + (size_t)(bx * BNT) * DIM;

    const uint32_t sAaddr = smem_u32(&sA[0][0]);
    const uint32_t sBaddr = smem_u32(&sB[0][0]);
    const uint32_t stageBytes = BMT * SSTR * 4;

    float acc[4][4][4];
#pragma unroll
    for (int i = 0; i < 4; i++)
#pragma unroll
        for (int j = 0; j < 4; j++)
#pragma unroll
            for (int e = 0; e < 4; e++) acc[i][j][e] = 0.0f;

    auto load_stage = [&](int st, int kt) {
#pragma unroll
        for (int i = 0; i < 2; i++) {
            int idx = tid + i * 256;
            int row = idx >> 2, c = idx & 3;
            uint32_t off = (uint32_t)(row * SSTR + c * 4) * 4;
            cp16(sAaddr + st * stageBytes + off,
                 Abase + (size_t)row * DIM + kt + c * 4);
            cp16(sBaddr + st * stageBytes + off,
                 Bbase + (size_t)row * DIM + kt + c * 4);
        }
    };

    load_stage(0, 0);
    CP_COMMIT();

    const int KITERS = DIM / BKT;
    for (int it = 0; it < KITERS; it++) {
        int nxt = it + 1;
        if (nxt < KITERS) load_stage(nxt & 1, nxt * BKT);
        CP_COMMIT();
        CP_WAIT1();
        __syncthreads();

        const float* a_s = sA[it & 1];
        const float* b_s = sB[it & 1];

        uint32_t Ahi[4][4], Alo[4][4], Bhi[4][2], Blo[4][2];
#pragma unroll
        for (int mf = 0; mf < 4; mf++) {
            int r0 = wm * 64 + mf * 16 + g;
            float2 x0 = *(const float2*)&a_s[r0 * SSTR + 2 * t];
            float2 x1 = *(const float2*)&a_s[(r0 + 8) * SSTR + 2 * t];
            float2 x2 = *(const float2*)&a_s[r0 * SSTR + 2 * t + 8];
            float2 x3 = *(const float2*)&a_s[(r0 + 8) * SSTR + 2 * t + 8];
            split2(x0.x, x0.y, Ahi[mf][0], Alo[mf][0]);
            split2(x1.x, x1.y, Ahi[mf][1], Alo[mf][1]);
            split2(x2.x, x2.y, Ahi[mf][2], Alo[mf][2]);
            split2(x3.x, x3.y, Ahi[mf][3], Alo[mf][3]);
        }
#pragma unroll
        for (int nf = 0; nf < 4; nf++) {
            int n = wn * 32 + nf * 8 + g;
            float2 y0 = *(const float2*)&b_s[n * SSTR + 2 * t];
            float2 y1 = *(const float2*)&b_s[n * SSTR + 2 * t + 8];
            split2(y0.x, y0.y, Bhi[nf][0], Blo[nf][0]);
            split2(y1.x, y1.y, Bhi[nf][1], Blo[nf][1]);
        }

#pragma unroll
        for (int mf = 0; mf < 4; mf++)
#pragma unroll
            for (int nf = 0; nf < 4; nf++) {
                float* c = acc[mf][nf];
                mma_bf16(c, Ahi[mf][0], Ahi[mf][1], Ahi[mf][2], Ahi[mf][3],
                         Bhi[nf][0], Bhi[nf][1]);
                mma_bf16(c, Ahi[mf][0], Ahi[mf][1], Ahi[mf][2], Ahi[mf][3],
                         Blo[nf][0], Blo[nf][1]);
                mma_bf16(c, Alo[mf][0], Alo[mf][1], Alo[mf][2], Alo[mf][3],
                         Bhi[nf][0], Bhi[nf][1]);
            }
        __syncthreads();
    }

#pragma unroll
    for (int mf = 0; mf < 4; mf++) {
#pragma unroll
        for (int nf = 0; nf < 4; nf++) {
            int row0 = by * BMT + wm * 64 + mf * 16 + g;
            int col = bx * BNT + wn * 32 + nf * 8 + 2 * t;
            float b0 = bias[col], b1 = bias[col + 1];
            float2 o0, o1;
            o0.x = acc[mf][nf][0] + b0; o0.y = acc[mf][nf][1] + b1;
            o1.x = acc[mf][nf][2] + b0; o1.y = acc[mf][nf][3] + b1;
            *(float2*)(C + (size_t)row0 * DIM + col) = o0;
            *(float2*)(C + (size_t)(row0 + 8) * DIM + col) = o1;
        }
    }
}

// Fused Q/K/V projections: blockIdx.z selects which projection.
__global__ __launch_bounds__(256, 1) void gemm_qkv(
    const float* __restrict__ q, const float* __restrict__ k,
    const float* __restrict__ v,
    const float* __restrict__ Wq, const float* __restrict__ Wk,
    const float* __restrict__ Wv,
    const float* __restrict__ bq, const float* __restrict__ bk,
    const float* __restrict__ bv,
    float* __restrict__ Cq, float* __restrict__ Ck, float* __restrict__ Cv)
{
    const int z = blockIdx.z;
    const float* A = (z == 0) ? q : (z == 1) ? k : v;
    const float* W = (z == 0) ? Wq : (z == 1) ? Wk : Wv;
    const float* bi = (z == 0) ? bq : (z == 1) ? bk : bv;
    float* C = (z == 0) ? Cq : (z == 1) ? Ck : Cv;
    gemm_body(A, W, bi, C);
}

__global__ __launch_bounds__(256, 1) void gemm_one(
    const float* __restrict__ A, const float* __restrict__ Bm,
    const float* __restrict__ bias, float* __restrict__ C)
{
    gemm_body(A, Bm, bias, C);
}

// ===========================================================================
// Tensor-core flash attention (round-6 structure; ldmatrix.x4 B-fragments).
// Block: 128 q rows x one (b,h), 256 threads, K-tile = 64 tokens,
// double-buffered K/V smem, 1 sync/tile.
// ===========================================================================
#define KSTR 72                      // halfs per smem row (144 bytes)
#define KVSTRIDE (4 * 64 * KSTR)     // halfs per KV stage (KH,KL,VH,VL)
#define ATT_SMEM ((2 * 128 * KSTR + 2 * KVSTRIDE) * 2)   // bytes

__global__ __launch_bounds__(256, 1) void flash_attn_mma(
    const float* __restrict__ Q, const float* __restrict__ Kg,
    const float* __restrict__ Vg, float* __restrict__ O)
{
    extern __shared__ __nv_bfloat16 smem[];
    __nv_bfloat16* QH = smem;
    __nv_bfloat16* QL = QH + 128 * KSTR;
    __nv_bfloat16* KV = QL + 128 * KSTR;   // 2 stages of [KH|KL|VH|VL]

    const int tid = threadIdx.x;
    const int lane = tid & 31;
    const int w = tid >> 5;
    const int g = lane >> 2;
    const int t = lane & 3;

    const int bh = blockIdx.y;
    const int b = bh >> 4, h = bh & 15;
    const int q0 = blockIdx.x * 128;

    const size_t bhOff = (size_t)b * SEQ * DIM + (size_t)h * HDIM;
    const float* Qb = Q + bhOff;
    const float* Kb = Kg + bhOff;
    const float* Vb = Vg + bhOff;

    // ldmatrix per-lane static offset: sel 0..3 -> [hi k0-7 | hi k8-15 |
    // lo k0-7 | lo k8-15]; row = lane&7 within the 8-token/8-dim group.
    const int lrow = lane & 7, lsel = lane >> 3;
    const uint32_t kvu32 = smem_u32(KV);
    const uint32_t laneoff =
        (uint32_t)(lrow * KSTR + (lsel & 1) * 8 + (lsel >> 1) * (64 * KSTR)) * 2;

    const int ktok = tid >> 2, kdg = tid & 3;     // K: 64 tok x 4 thr
    const int vdb = tid >> 6, vtok = tid & 63;    // V: 4 dim-grp x 64 tok
    float kr[16], vr[16];

    auto loadKV = [&](int kt) {
        const float* ks = Kb + (size_t)(kt + ktok) * DIM + kdg * 16;
        const float* vs = Vb + (size_t)(kt + vtok) * DIM + vdb * 16;
#pragma unroll
        for (int i = 0; i < 4; i++) {
            *(float4*)&kr[4 * i] = *(const float4*)(ks + 4 * i);
            *(float4*)&vr[4 * i] = *(const float4*)(vs + 4 * i);
        }
    };
    auto storeKV = [&](int stage) {
        __nv_bfloat16* KH = KV + stage * KVSTRIDE;
        __nv_bfloat16* KL = KH + 64 * KSTR;
        __nv_bfloat16* VH = KL + 64 * KSTR;
        __nv_bfloat16* VL = VH + 64 * KSTR;
        uint32_t* dh = (uint32_t*)(KH + ktok * KSTR + kdg * 16);
        uint32_t* dl = (uint32_t*)(KL + ktok * KSTR + kdg * 16);
#pragma unroll
        for (int p = 0; p < 8; p++) {
            uint32_t hi, lo;
            split2(kr[2 * p], kr[2 * p + 1], hi, lo);
            dh[p] = hi; dl[p] = lo;
        }
#pragma unroll
        for (int j = 0; j < 16; j++) {     // transposed V store
            float x = vr[j];
            __nv_bfloat16 hv = __float2bfloat16_rn(x);
            VH[(vdb * 16 + j) * KSTR + vtok] = hv;
            VL[(vdb * 16 + j) * KSTR + vtok] =
                __float2bfloat16_rn(x - __bfloat162float(hv));
        }
    };

    // ---- prologue: Q tile (scaled x8, split hi/lo) + K/V tile 0 ----
    {
        const int row = tid >> 1, half = tid & 1;
        const float* src = Qb + (size_t)(q0 + row) * DIM + half * 32;
        uint32_t* dh = (uint32_t*)(QH + row * KSTR + half * 32);
        uint32_t* dl = (uint32_t*)(QL + row * KSTR + half * 32);
#pragma unroll
        for (int i = 0; i < 8; i++) {
            float4 v = *(const float4*)(src + 4 * i);
            uint32_t h0, l0, h1, l1;
            split2(v.x * 8.0f, v.y * 8.0f, h0, l0);
            split2(v.z * 8.0f, v.w * 8.0f, h1, l1);
            dh[2 * i] = h0; dh[2 * i + 1] = h1;
            dl[2 * i] = l0; dl[2 * i + 1] = l1;
        }
    }
    loadKV(0);
    storeKV(0);
    __syncthreads();

    // ---- Q fragments (registers, live whole kernel) ----
    uint32_t qh[4][4], ql[4][4];
#pragma unroll
    for (int kf = 0; kf < 4; kf++) {
        const int r0 = w * 16 + g;
        qh[kf][0] = *(uint32_t*)(QH + r0 * KSTR + kf * 16 + 2 * t);
        qh[kf][1] = *(uint32_t*)(QH + (r0 + 8) * KSTR + kf * 16 + 2 * t);
        qh[kf][2] = *(uint32_t*)(QH + r0 * KSTR + kf * 16 + 8 + 2 * t);
        qh[kf][3] = *(uint32_t*)(QH + (r0 + 8) * KSTR + kf * 16 + 8 + 2 * t);
        ql[kf][0] = *(uint32_t*)(QL + r0 * KSTR + kf * 16 + 2 * t);
        ql[kf][1] = *(uint32_t*)(QL + (r0 + 8) * KSTR + kf * 16 + 2 * t);
        ql[kf][2] = *(uint32_t*)(QL + r0 * KSTR + kf * 16 + 8 + 2 * t);
        ql[kf][3] = *(uint32_t*)(QL + (r0 + 8) * KSTR + kf * 16 + 8 + 2 * t);
    }

    float m0 = -INFINITY, m1 = -INFINITY, l0 = 0.0f, l1 = 0.0f;
    float acc[8][4];
#pragma unroll
    for (int nf = 0; nf < 8; nf++)
#pragma unroll
        for (int e = 0; e < 4; e++) acc[nf][e] = 0.0f;

    const int NTILES = SEQ / 64;   // 32
    for (int it = 0; it < NTILES; it++) {
        const int stage = it & 1;
        const uint32_t kbase = kvu32 + (uint32_t)(stage * KVSTRIDE) * 2 + laneoff;
        const uint32_t vbase = kbase + (uint32_t)(2 * 64 * KSTR) * 2;

        if (it + 1 < NTILES) loadKV((it + 1) * 64);

        // ---- scores S[16x64] ----
        float s[8][4];
#pragma unroll
        for (int nf = 0; nf < 8; nf++)
#pragma unroll
            for (int e = 0; e < 4; e++) s[nf][e] = 0.0f;

#pragma unroll
        for (int nf = 0; nf < 8; nf++) {
            const uint32_t rowb = kbase + (uint32_t)(nf * 8 * KSTR) * 2;
#pragma unroll
            for (int kf = 0; kf < 4; kf++) {
                uint32_t f[4];
                ldmx4(f, rowb + (uint32_t)(kf * 16) * 2);
                mma_bf16(s[nf], qh[kf][0], qh[kf][1], qh[kf][2], qh[kf][3], f[0], f[1]);
                mma_bf16(s[nf], ql[kf][0], ql[kf][1], ql[kf][2], ql[kf][3], f[0], f[1]);
                mma_bf16(s[nf], qh[kf][0], qh[kf][1], qh[kf][2], qh[kf][3], f[2], f[3]);
            }
        }

        // ---- online softmax (rows g and g+8) ----
        float tm0 = -INFINITY, tm1 = -INFINITY;
#pragma unroll
        for (int nf = 0; nf < 8; nf++) {
            tm0 = fmaxf(tm0, fmaxf(s[nf][0], s[nf][1]));
            tm1 = fmaxf(tm1, fmaxf(s[nf][2], s[nf][3]));
        }
        tm0 = fmaxf(tm0, __shfl_xor_sync(0xffffffffu, tm0, 1));
        tm0 = fmaxf(tm0, __shfl_xor_sync(0xffffffffu, tm0, 2));
        tm1 = fmaxf(tm1, __shfl_xor_sync(0xffffffffu, tm1, 1));
        tm1 = fmaxf(tm1, __shfl_xor_sync(0xffffffffu, tm1, 2));

        float mn0 = fmaxf(m0, tm0), mn1 = fmaxf(m1, tm1);
        float c0 = __expf(m0 - mn0), c1 = __expf(m1 - mn1);
        m0 = mn0; m1 = mn1;

        float ls0 = 0.0f, ls1 = 0.0f;
#pragma unroll
        for (int nf = 0; nf < 8; nf++) {
            s[nf][0] = __expf(s[nf][0] - mn0);
            s[nf][1] = __expf(s[nf][1] - mn0);
            s[nf][2] = __expf(s[nf][2] - mn1);
            s[nf][3] = __expf(s[nf][3] - mn1);
            ls0 += s[nf][0] + s[nf][1];
            ls1 += s[nf][2] + s[nf][3];
        }
        ls0 += __shfl_xor_sync(0xffffffffu, ls0, 1);
        ls0 += __shfl_xor_sync(0xffffffffu, ls0, 2);
        ls1 += __shfl_xor_sync(0xffffffffu, ls1, 1);
        ls1 += __shfl_xor_sync(0xffffffffu, ls1, 2);
        l0 = l0 * c0 + ls0;
        l1 = l1 * c1 + ls1;

#pragma unroll
        for (int nf = 0; nf < 8; nf++) {
            acc[nf][0] *= c0; acc[nf][1] *= c0;
            acc[nf][2] *= c1; acc[nf][3] *= c1;
        }

        // ---- pack P into A-fragments (registers only) ----
        uint32_t ph[4][4], pl[4][4];
#pragma unroll
        for (int kf = 0; kf < 4; kf++) {
            const float* p0 = s[2 * kf];
            const float* p1 = s[2 * kf + 1];
            split2(p0[0], p0[1], ph[kf][0], pl[kf][0]);
            split2(p0[2], p0[3], ph[kf][1], pl[kf][1]);
            split2(p1[0], p1[1], ph[kf][2], pl[kf][2]);
            split2(p1[2], p1[3], ph[kf][3], pl[kf][3]);
        }

        // store next K/V tile into the other stage (writes target the buffer
        // nobody reads this iteration)
        if (it + 1 < NTILES) storeKV(stage ^ 1);

        // ---- acc += P * V ----
#pragma unroll
        for (int nf = 0; nf < 8; nf++) {
            const uint32_t rowb = vbase + (uint32_t)(nf * 8 * KSTR) * 2;
#pragma unroll
            for (int kf = 0; kf < 4; kf++) {
                uint32_t f[4];
                ldmx4(f, rowb + (uint32_t)(kf * 16) * 2);
                mma_bf16(acc[nf], ph[kf][0], ph[kf][1], ph[kf][2], ph[kf][3], f[0], f[1]);
                mma_bf16(acc[nf], pl[kf][0], pl[kf][1], pl[kf][2], pl[kf][3], f[0], f[1]);
                mma_bf16(acc[nf], ph[kf][0], ph[kf][1], ph[kf][2], ph[kf][3], f[2], f[3]);
            }
        }

        __syncthreads();
    }

    // ---- epilogue ----
    const float inv0 = 1.0f / l0;
    const float inv1 = 1.0f / l1;
    const int row0 = q0 + w * 16 + g;
    float* ob = O + bhOff;
#pragma unroll
    for (int nf = 0; nf < 8; nf++) {
        const int col = nf * 8 + 2 * t;
        float2 o0, o1;
        o0.x = acc[nf][0] * inv0; o0.y = acc[nf][1] * inv0;
        o1.x = acc[nf][2] * inv1; o1.y = acc[nf][3] * inv1;
        *(float2*)(ob + (size_t)row0 * DIM + col) = o0;
        *(float2*)(ob + (size_t)(row0 + 8) * DIM + col) = o1;
    }
}

// ---------------------------------------------------------------------------
extern "C" void kernel_launch(void* const* d_in, const int* in_sizes, int n_in,
                              void* d_out, int out_size)
{
    (void)in_sizes; (void)n_in; (void)out_size;
    const float* query = (const float*)d_in[0];
    const float* key   = (const float*)d_in[1];
    const float* value = (const float*)d_in[2];
    const float* Wq = (const float*)d_in[3];
    const float* bq = (const float*)d_in[4];
    const float* Wk = (const float*)d_in[5];
    const float* bk = (const float*)d_in[6];
    const float* Wv = (const float*)d_in[7];
    const float* bv = (const float*)d_in[8];
    const float* Wo = (const float*)d_in[9];
    const float* bo = (const float*)d_in[10];
    float* out = (float*)d_out;

    float *qbuf, *kbuf, *vbuf, *abuf;
    cudaGetSymbolAddress((void**)&qbuf, g_Q);
    cudaGetSymbolAddress((void**)&kbuf, g_K);
    cudaGetSymbolAddress((void**)&vbuf, g_V);
    cudaGetSymbolAddress((void**)&abuf, g_A);

    static bool attrSet = false;
    if (!attrSet) {
        cudaFuncSetAttribute(flash_attn_mma,
                             cudaFuncAttributeMaxDynamicSharedMemorySize,
                             ATT_SMEM);
        attrSet = true;
    }

    dim3 qkvGrid(DIM / 128, MROWS / 128, 3);   // (8, 32, 3)
    gemm_qkv<<<qkvGrid, 256>>>(query, key, value, Wq, Wk, Wv,
                               bq, bk, bv, qbuf, kbuf, vbuf);

    dim3 attnGrid(SEQ / 128, BATCH * HEADS);   // (16, 32)
    flash_attn_mma<<<attnGrid, 256, ATT_SMEM>>>(qbuf, kbuf, vbuf, abuf);

    dim3 gemmGrid(DIM / 128, MROWS / 128);     // (8, 32)
    gemm_one<<<gemmGrid, 256>>>(abuf, Wo, bo, out);
}